// round 16
// baseline (speedup 1.0000x reference)
#include <cuda_runtime.h>
#include <cuda_fp16.h>
#include <cuda_bf16.h>

// pri scratch: [t_global (1152)][b (64)][n*16+d (512)] fp16 = 75.5 MB
static __device__ __half g_pri[37748736];

// ---------------------------------------------------------------------------
// Kernel 1: pri = x_t @ W_t via single-pass tf32 MMA (m16n8k8, RNA-rounded).
// CTA = (t, nd-half). 87KB smem -> 2 CTAs/SM. (Measured 60us in R15.)
// ---------------------------------------------------------------------------
#define WS_WORDS (256 * 68)
#define XS_OFF   (WS_WORDS * 4)
#define K_PRI_SMEM (WS_WORDS * 4 + 64 * 68 * 4)   // 87040
#define SC 264

__device__ __forceinline__ unsigned to_tf32(float x) {
    unsigned r;
    asm("cvt.rna.tf32.f32 %0, %1;" : "=r"(r) : "f"(x));
    return r;
}

__device__ __forceinline__ void mma_tf32(float* c, const unsigned* a,
                                         unsigned b0, unsigned b1) {
    asm volatile(
        "mma.sync.aligned.m16n8k8.row.col.f32.tf32.tf32.f32 "
        "{%0,%1,%2,%3}, {%4,%5,%6,%7}, {%8,%9}, {%0,%1,%2,%3};"
        : "+f"(c[0]), "+f"(c[1]), "+f"(c[2]), "+f"(c[3])
        : "r"(a[0]), "r"(a[1]), "r"(a[2]), "r"(a[3]), "r"(b0), "r"(b1));
}

__global__ __launch_bounds__(512, 2) void k_pri(
    const float* __restrict__ xT, const float* __restrict__ xA,
    const float* __restrict__ xV, const float* __restrict__ xF,
    const float* __restrict__ wT, const float* __restrict__ wA,
    const float* __restrict__ wV, const float* __restrict__ wF)
{
    extern __shared__ char smc[];
    unsigned* Ws = reinterpret_cast<unsigned*>(smc);
    unsigned* Xs = reinterpret_cast<unsigned*>(smc + XS_OFF);
    __half*   Cs = reinterpret_cast<__half*>(smc);

    int bid  = blockIdx.x;
    int tg   = bid >> 1;
    int half = bid & 1;
    const float* x; const float* w; int T, t;
    if (tg < 128)      { x = xT; w = wT; T = 128; t = tg;       }
    else if (tg < 640) { x = xA; w = wA; T = 512; t = tg - 128; }
    else if (tg < 896) { x = xV; w = wV; T = 256; t = tg - 640; }
    else               { x = xF; w = wF; T = 256; t = tg - 896; }

    int tid = threadIdx.x;

    #pragma unroll
    for (int u = tid; u < 2048; u += 512) {
        int bb = u >> 5, jp = u & 31;
        float2 v2 = *reinterpret_cast<const float2*>(
            x + ((size_t)bb * T + t) * 64 + jp * 2);
        uint2 st; st.x = to_tf32(v2.x); st.y = to_tf32(v2.y);
        *reinterpret_cast<uint2*>(&Xs[bb * 68 + jp * 2]) = st;
    }

    const float4* w4 = reinterpret_cast<const float4*>(w + (size_t)t * 32768);
    #pragma unroll
    for (int u = tid; u < 2048; u += 512) {
        int d0c = u & 3;
        int jp  = (u >> 2) & 31;
        int nl  = u >> 7;
        int nbase = (half * 16 + nl) * 256 + jp * 8 + d0c;
        float4 va = __ldg(w4 + nbase);
        float4 vb = __ldg(w4 + nbase + 4);
        float aa[4] = {va.x, va.y, va.z, va.w};
        float bb4[4] = {vb.x, vb.y, vb.z, vb.w};
        #pragma unroll
        for (int q = 0; q < 4; q++) {
            int row = (nl << 4) + d0c * 4 + q;
            uint2 st; st.x = to_tf32(aa[q]); st.y = to_tf32(bb4[q]);
            *reinterpret_cast<uint2*>(&Ws[row * 68 + jp * 2]) = st;
        }
    }
    __syncthreads();

    int lane = tid & 31, wrp = tid >> 5;
    int g  = lane >> 2;
    int tq = lane & 3;
    int mbase  = (wrp & 1) * 32;
    int ndbase = (wrp >> 1) * 32;

    float acc[2][4][4];
    #pragma unroll
    for (int mt = 0; mt < 2; mt++)
        #pragma unroll
        for (int nt = 0; nt < 4; nt++)
            #pragma unroll
            for (int q = 0; q < 4; q++) acc[mt][nt][q] = 0.f;

    #pragma unroll
    for (int k0 = 0; k0 < 64; k0 += 8) {
        unsigned a[2][4];
        #pragma unroll
        for (int mt = 0; mt < 2; mt++) {
            int r0 = mbase + mt * 16 + g;
            int kc = k0 + tq;
            a[mt][0] = Xs[r0 * 68 + kc];
            a[mt][1] = Xs[(r0 + 8) * 68 + kc];
            a[mt][2] = Xs[r0 * 68 + kc + 4];
            a[mt][3] = Xs[(r0 + 8) * 68 + kc + 4];
        }
        #pragma unroll
        for (int nt = 0; nt < 4; nt++) {
            int col = ndbase + nt * 8 + g;
            int kc  = k0 + tq;
            unsigned b0 = Ws[col * 68 + kc];
            unsigned b1 = Ws[col * 68 + kc + 4];
            #pragma unroll
            for (int mt = 0; mt < 2; mt++)
                mma_tf32(acc[mt][nt], a[mt], b0, b1);
        }
    }
    __syncthreads();

    #pragma unroll
    for (int mt = 0; mt < 2; mt++)
        #pragma unroll
        for (int nt = 0; nt < 4; nt++) {
            int r0 = mbase + mt * 16 + g;
            int c0 = ndbase + nt * 8 + tq * 2;
            __half2 lo = __floats2half2_rn(acc[mt][nt][0], acc[mt][nt][1]);
            __half2 hi = __floats2half2_rn(acc[mt][nt][2], acc[mt][nt][3]);
            *(__half2*)&Cs[r0 * SC + c0]       = lo;
            *(__half2*)&Cs[(r0 + 8) * SC + c0] = hi;
        }
    __syncthreads();

    __half* base = g_pri + (size_t)tg * 64 * 512 + half * 256;
    #pragma unroll
    for (int i = tid; i < 2048; i += 512) {
        int bb = i >> 5, off = i & 31;
        *reinterpret_cast<uint4*>(base + bb * 512 + off * 8) =
            *(const uint4*)&Cs[bb * SC + off * 8];
    }
}

// ---------------------------------------------------------------------------
// Kernel 2: fused dynamic routing, 1024 threads / 32 warps per (m,b) CTA.
// V-trick (beta-free, logit = accumulated-V . p) + 2-way t-interleave.
// Halves chain-pairs per warp vs 16-warp layout. Dynamic smem 70KB.
// ---------------------------------------------------------------------------
#define RT_SMEM (32 * 512 * 4 + 2 * 512 * 4 + 32 * 17 * 4)   // 70272

__device__ __forceinline__ void ld_raw(int tglob, int b, int lane,
                                       uint4& ua, uint4& ub) {
    const __half* pp = g_pri + (((size_t)(tglob * 64 + b)) << 9) + (lane << 4);
    ua = __ldg((const uint4*)pp);
    ub = __ldg((const uint4*)(pp + 8));
}

__device__ __forceinline__ float dot_raw(const float* v, uint4 ua, uint4 ub) {
    const __half2* ha = reinterpret_cast<const __half2*>(&ua);
    const __half2* hb = reinterpret_cast<const __half2*>(&ub);
    float s0 = 0.f, s1 = 0.f, s2 = 0.f, s3 = 0.f;
    #pragma unroll
    for (int k = 0; k < 4; k++) {
        float2 fa = __half22float2(ha[k]);
        float2 fb = __half22float2(hb[k]);
        s0 = fmaf(v[2 * k],         fa.x, s0);
        s1 = fmaf(v[2 * k + 1],     fa.y, s1);
        s2 = fmaf(v[8 + 2 * k],     fb.x, s2);
        s3 = fmaf(v[8 + 2 * k + 1], fb.y, s3);
    }
    return (s0 + s1) + (s2 + s3);
}

__device__ __forceinline__ void s_upd(float* s, float r, uint4 ua, uint4 ub) {
    const __half2* ha = reinterpret_cast<const __half2*>(&ua);
    const __half2* hb = reinterpret_cast<const __half2*>(&ub);
    #pragma unroll
    for (int k = 0; k < 4; k++) {
        float2 fa = __half22float2(ha[k]);
        float2 fb = __half22float2(hb[k]);
        s[2 * k]         = fmaf(r, fa.x, s[2 * k]);
        s[2 * k + 1]     = fmaf(r, fa.y, s[2 * k + 1]);
        s[8 + 2 * k]     = fmaf(r, fb.x, s[8 + 2 * k]);
        s[8 + 2 * k + 1] = fmaf(r, fb.y, s[8 + 2 * k + 1]);
    }
}

// cross-warp reduce (32 rows) + tanh + broadcast. kind: 0 = scale 1/32 set V,
// 1 = add to V, 2 = final store.
template<int NT>
__device__ __forceinline__ void route_body(int b, int t0, float* __restrict__ outm,
                                           float* red, float* part, float* vsm)
{
    int tid  = threadIdx.x;
    int w    = tid >> 5;
    int lane = tid & 31;
    int j    = tid & 511;
    int hf   = tid >> 9;

    float V[16];

    // ---- pass 0: v1 = tanh(sum_t pri / 32) ----
    {
        float s[16];
        #pragma unroll
        for (int d = 0; d < 16; d++) s[d] = 0.f;
        #pragma unroll 1
        for (int i = 0; i < NT; i += 2) {
            uint4 ua0, ub0, ua1, ub1;
            ld_raw(t0 + w + (i << 5),       b, lane, ua0, ub0);
            ld_raw(t0 + w + ((i + 1) << 5), b, lane, ua1, ub1);
            s_upd(s, 1.0f, ua0, ub0);
            s_upd(s, 1.0f, ua1, ub1);
        }
        #pragma unroll
        for (int d = 0; d < 16; d++) red[w * 512 + (lane << 4) + d] = s[d];
        __syncthreads();
        float p = 0.f;
        #pragma unroll
        for (int ww = 0; ww < 16; ww++) p += red[(hf * 16 + ww) * 512 + j];
        part[hf * 512 + j] = p;
        __syncthreads();
        if (tid < 512) {
            float tot = part[tid] + part[512 + tid];
            vsm[(tid >> 4) * 17 + (tid & 15)] = tanhf(tot * (1.0f / 32.0f));
        }
        __syncthreads();
        #pragma unroll
        for (int d = 0; d < 16; d++) V[d] = vsm[lane * 17 + d];
        __syncthreads();
    }

    // ---- 3 routing iterations; logit = V . p (linear accumulation) ----
    #pragma unroll 1
    for (int it = 0; it < 3; it++) {
        float s[16];
        #pragma unroll
        for (int d = 0; d < 16; d++) s[d] = 0.f;
        #pragma unroll 1
        for (int i = 0; i < NT; i += 2) {
            uint4 ua0, ub0, ua1, ub1;
            ld_raw(t0 + w + (i << 5),       b, lane, ua0, ub0);
            ld_raw(t0 + w + ((i + 1) << 5), b, lane, ua1, ub1);

            float b0 = dot_raw(V, ua0, ub0);
            float b1 = dot_raw(V, ua1, ub1);
            float e0 = __expf(b0), e1 = __expf(b1);
            float Z0 = e0, Z1 = e1;
            #pragma unroll
            for (int off = 16; off > 0; off >>= 1) {
                Z0 += __shfl_xor_sync(0xffffffffu, Z0, off);
                Z1 += __shfl_xor_sync(0xffffffffu, Z1, off);
            }
            s_upd(s, __fdividef(e0, Z0), ua0, ub0);
            s_upd(s, __fdividef(e1, Z1), ua1, ub1);
        }
        #pragma unroll
        for (int d = 0; d < 16; d++) red[w * 512 + (lane << 4) + d] = s[d];
        __syncthreads();
        float p = 0.f;
        #pragma unroll
        for (int ww = 0; ww < 16; ww++) p += red[(hf * 16 + ww) * 512 + j];
        part[hf * 512 + j] = p;
        __syncthreads();
        if (it == 2) {
            if (tid < 512) {
                float tot = part[tid] + part[512 + tid];
                outm[(b << 9) + tid] = tanhf(tot);
            }
        } else {
            if (tid < 512) {
                float tot = part[tid] + part[512 + tid];
                vsm[(tid >> 4) * 17 + (tid & 15)] = tanhf(tot);
            }
            __syncthreads();
            #pragma unroll
            for (int d = 0; d < 16; d++) V[d] += vsm[lane * 17 + d];
            __syncthreads();
        }
    }
}

__global__ __launch_bounds__(1024, 1) void k_route(float* __restrict__ out)
{
    extern __shared__ float rsm[];
    float* red  = rsm;                 // 32 x 512
    float* part = red + 32 * 512;      // 2 x 512
    float* vsm  = part + 2 * 512;      // 32 x 17
    int m = blockIdx.x >> 6;
    int b = blockIdx.x & 63;
    if      (m == 0) route_body<4 >(b,   0, out,          red, part, vsm);
    else if (m == 1) route_body<16>(b, 128, out + 32768,  red, part, vsm);
    else if (m == 2) route_body<8 >(b, 640, out + 65536,  red, part, vsm);
    else             route_body<8 >(b, 896, out + 98304,  red, part, vsm);
}

extern "C" void kernel_launch(void* const* d_in, const int* in_sizes, int n_in,
                              void* d_out, int out_size)
{
    const float* xT = (const float*)d_in[0];
    const float* xA = (const float*)d_in[1];
    const float* xV = (const float*)d_in[2];
    const float* xF = (const float*)d_in[3];
    const float* wT = (const float*)d_in[4];
    const float* wA = (const float*)d_in[5];
    const float* wV = (const float*)d_in[6];
    const float* wF = (const float*)d_in[7];

    // Unconditional (no static guard): idempotent, allocation-free, immediate.
    cudaFuncSetAttribute(k_pri, cudaFuncAttributeMaxDynamicSharedMemorySize,
                         K_PRI_SMEM);
    cudaFuncSetAttribute(k_route, cudaFuncAttributeMaxDynamicSharedMemorySize,
                         RT_SMEM);

    k_pri  <<<2304, 512, K_PRI_SMEM>>>(xT, xA, xV, xF, wT, wA, wV, wF);
    k_route<<<256, 1024, RT_SMEM>>>((float*)d_out);
}